// round 17
// baseline (speedup 1.0000x reference)
#include <cuda_runtime.h>
#include <cuda_fp16.h>
#include <math.h>
#include <stdint.h>

// Problem constants
#define B_      32
#define T_      64
#define V_      30000
#define E_      64
#define H_      64
#define O_      7
#define M_      2048
#define KSPLIT  18
#define KCHUNK  1728            // 27 * 64
#define BK      64
#define NTILES  486             // KSPLIT * 27 (covers ceil(30000/64)=469, rest zero)

// ---------------------------------------------------------------------------
// Scratch (device globals; no allocations allowed)
// ---------------------------------------------------------------------------
__device__ float g_partial[KSPLIT * M_ * E_];   // [s][row][n]
__device__ float g_rowsum[KSPLIT * M_];
__device__ float g_proj[3 * M_ * E_];
// Pre-swizzled fp16 W tiles: [tile][512 x uint4] = 8KB per 64k x 64n tile
__device__ uint4 g_whi[NTILES * 512];

// ---------------------------------------------------------------------------
// MMA helpers (warp-level HMMA fp16, fp32 accum)
// ---------------------------------------------------------------------------
__device__ __forceinline__ void ldsm_x4(uint32_t* r, uint32_t addr) {
    asm volatile("ldmatrix.sync.aligned.m8n8.x4.shared.b16 {%0,%1,%2,%3}, [%4];"
        : "=r"(r[0]), "=r"(r[1]), "=r"(r[2]), "=r"(r[3]) : "r"(addr));
}
__device__ __forceinline__ void ldsm_x4_t(uint32_t* r, uint32_t addr) {
    asm volatile("ldmatrix.sync.aligned.m8n8.x4.trans.shared.b16 {%0,%1,%2,%3}, [%4];"
        : "=r"(r[0]), "=r"(r[1]), "=r"(r[2]), "=r"(r[3]) : "r"(addr));
}
__device__ __forceinline__ void mma_f16(float* d, const uint32_t* a,
                                        uint32_t b0, uint32_t b1) {
    asm volatile("mma.sync.aligned.m16n8k16.row.col.f32.f16.f16.f32 "
        "{%0,%1,%2,%3}, {%4,%5,%6,%7}, {%8,%9}, {%0,%1,%2,%3};"
        : "+f"(d[0]), "+f"(d[1]), "+f"(d[2]), "+f"(d[3])
        : "r"(a[0]), "r"(a[1]), "r"(a[2]), "r"(a[3]), "r"(b0), "r"(b1));
}
// pack two fp32 -> fp16x2 word, low half = first arg
__device__ __forceinline__ uint32_t pack_f16(float lo, float hi) {
    uint32_t w;
    asm("cvt.rn.f16x2.f32 %0, %1, %2;" : "=r"(w) : "f"(hi), "f"(lo));
    return w;
}
__device__ __forceinline__ void cp_async16(uint32_t smem_dst, const void* gsrc) {
    asm volatile("cp.async.cg.shared.global [%0], [%1], 16;"
        :: "r"(smem_dst), "l"(gsrc) : "memory");
}

// ---------------------------------------------------------------------------
// Kernel 0: W prep. W (V x 64 fp32) -> fp16 tiles, SW128-swizzled,
//   ldsm-ready 8KB per 64k x 64n tile. One block per tile.
// ---------------------------------------------------------------------------
__global__ void __launch_bounds__(256) k_wsplit(const float* __restrict__ w)
{
    const int t   = blockIdx.x;
    const int tid = threadIdx.x;
    const int np  = tid & 31;      // n-pair index (cols 2np, 2np+1)
    const int rq  = tid >> 5;      // 0..7

    char* hib_base = (char*)g_whi + (size_t)t * 8192;

    #pragma unroll
    for (int i = 0; i < 8; i++) {
        int kr = i * 8 + rq;                 // 0..63
        int kg = t * 64 + kr;
        float2 v = make_float2(0.f, 0.f);
        if (kg < V_) v = *(const float2*)(w + (size_t)kg * 64 + 2 * np);
        __half h0 = __float2half_rn(v.x), h1 = __float2half_rn(v.y);
        uint32_t hib = (uint32_t)__half_as_ushort(h0) |
                       ((uint32_t)__half_as_ushort(h1) << 16);
        uint32_t off = (uint32_t)(kr * 128 + np * 4);
        uint32_t sw  = off ^ ((kr & 7) << 4);
        *(uint32_t*)(hib_base + sw) = hib;
    }
}

// ---------------------------------------------------------------------------
// Kernel 1: split-K embed GEMM (HMMA fp16, single product), fully pipelined:
//   - sA double-buffered (one barrier per iteration)
//   - x register prefetch 2 tiles ahead (full-iteration latency window)
//   - sB 3-stage cp.async ring, committed 2 tiles ahead
//   CTA: M=128 x N=64, BK=64; 8 warps, each m16 x n64. Grid 16x18 = 1 wave.
// ---------------------------------------------------------------------------
__global__ void __launch_bounds__(256, 2) k_embed_gemm(const float* __restrict__ x)
{
    __shared__ __align__(128) unsigned char sA[2][16384];  // x fp16 tiles
    __shared__ __align__(128) unsigned char sB[3][8192];   // W fp16 ring

    const uint32_t aBase = (uint32_t)__cvta_generic_to_shared(sA);
    const uint32_t bBase = (uint32_t)__cvta_generic_to_shared(sB);

    const int tid = threadIdx.x;
    const int wr  = tid >> 5;          // warp id -> rows wr*16..+16
    const int l   = tid & 31;
    const int rt  = blockIdx.x;        // 16 row tiles
    const int s   = blockIdx.y;        // 18 k splits
    const int row0  = rt * 128;
    const int tile0 = s * 27;

    // x-load mapping: row = tid>>1, 8 float4 groups starting at (tid&1)*8
    const int xrow = tid >> 1;
    const int xcg  = (tid & 1) * 8;

    // ldmatrix lane geometry
    const int ml = l >> 3;
    const int a_sub  = (ml & 1) * 8 + (l & 7);
    const int a_coff = (ml >> 1) * 16;
    const int b_krow_sub = ((l >> 3) & 1) * 8 + (l & 7);
    const int b_noff     = ((l >> 4) & 1) * 16;

    float d[8][4];
    #pragma unroll
    for (int g = 0; g < 8; g++)
        #pragma unroll
        for (int i = 0; i < 4; i++) d[g][i] = 0.f;
    float rsum = 0.f;
    float4 xv[8];

    // ---- helpers as macros over locals ----
#define LOAD_X(TI)                                                            \
    {                                                                         \
        const int kb = (tile0 + (TI)) * 64;                                   \
        const float* xp = x + (size_t)(row0 + xrow) * V_ + kb;                \
        _Pragma("unroll")                                                     \
        for (int i = 0; i < 8; i++) {                                         \
            int c = 4 * (xcg + i);                                            \
            xv[i] = (kb + c < V_) ? __ldcs((const float4*)(xp + c))           \
                                  : make_float4(0.f, 0.f, 0.f, 0.f);          \
        }                                                                     \
    }
#define CONV_STORE(BUFIDX)                                                    \
    {                                                                         \
        unsigned char* dst = sA[(BUFIDX)];                                    \
        _Pragma("unroll")                                                     \
        for (int i = 0; i < 8; i++) {                                         \
            uint32_t off = (uint32_t)(xrow * 128 + 8 * (xcg + i));            \
            uint32_t sw  = off ^ ((xrow & 7) << 4);                           \
            uint32_t w0 = pack_f16(xv[i].x, xv[i].y);                         \
            uint32_t w1 = pack_f16(xv[i].z, xv[i].w);                         \
            *(uint2*)(dst + sw) = make_uint2(w0, w1);                         \
            rsum += (xv[i].x + xv[i].y) + (xv[i].z + xv[i].w);                \
        }                                                                     \
    }
#define CP_W(TI, STAGE)                                                       \
    {                                                                         \
        const uint4* src = g_whi + (size_t)(tile0 + (TI)) * 512;              \
        const uint32_t db = bBase + (STAGE) * 8192;                           \
        _Pragma("unroll")                                                     \
        for (int j = 0; j < 2; j++) {                                         \
            int idx = tid + 256 * j;                                          \
            cp_async16(db + idx * 16, src + idx);                             \
        }                                                                     \
        asm volatile("cp.async.commit_group;" ::: "memory");                  \
    }

    // ---- prologue ----
    CP_W(0, 0);
    CP_W(1, 1);
    LOAD_X(0);
    CONV_STORE(0);
    LOAD_X(1);
    asm volatile("cp.async.wait_group 1;" ::: "memory");   // W(0) ready
    __syncthreads();

    int b_cur = 0;       // it % 3
    int b_pf  = 2;       // (it+2) % 3
    for (int it = 0; it < 27; it++) {
        // 1) prefetch W(it+2) into ring stage (freed by mma(it-1), synced)
        if (it <= 24) CP_W(it + 2, b_pf);
        // 2) convert x(it+1) from regs into the other A buffer
        if (it < 26) CONV_STORE((it + 1) & 1);
        // 3) issue x(it+2) loads (consumed next iteration -> full-iter window)
        if (it <= 24) LOAD_X(it + 2);

        // 4) mma on sA[it&1], sB[it%3]
        {
            const unsigned char* aT = sA[it & 1];
            const uint32_t aB2 = aBase + (uint32_t)((it & 1) * 16384);
            const uint32_t bB2 = bBase + (uint32_t)(b_cur * 8192);
            (void)aT;
            #pragma unroll
            for (int kk = 0; kk < 4; kk++) {
                uint32_t a[4];
                {
                    int row = wr * 16 + a_sub;
                    uint32_t off = (uint32_t)(row * 128 + kk * 32 + a_coff);
                    ldsm_x4(a, aB2 + (off ^ ((row & 7) << 4)));
                }
                #pragma unroll
                for (int nr = 0; nr < 4; nr++) {
                    int krow = kk * 16 + b_krow_sub;
                    uint32_t off = (uint32_t)(krow * 128 + nr * 32 + b_noff);
                    uint32_t sw  = off ^ ((krow & 7) << 4);
                    uint32_t bh[4];
                    ldsm_x4_t(bh, bB2 + sw);
                    mma_f16(d[nr * 2 + 0], a, bh[0], bh[1]);
                    mma_f16(d[nr * 2 + 1], a, bh[2], bh[3]);
                }
            }
        }

        // 5) guarantee W(it+1) arrived before next iteration's mma
        if (it <= 24) {
            asm volatile("cp.async.wait_group 1;" ::: "memory");
        } else {
            asm volatile("cp.async.wait_group 0;" ::: "memory");
        }
        __syncthreads();

        b_cur = (b_cur == 2) ? 0 : b_cur + 1;
        b_pf  = (b_pf == 2) ? 0 : b_pf + 1;
    }

    // ---- epilogue: write partial tile ----
    {
        int r0 = row0 + wr * 16 + (l >> 2);
        #pragma unroll
        for (int g = 0; g < 8; g++) {
            int col = g * 8 + (l & 3) * 2;
            size_t base = ((size_t)s * M_ + r0) * 64 + col;
            *(float2*)(g_partial + base)       = make_float2(d[g][0], d[g][1]);
            *(float2*)(g_partial + base + 512) = make_float2(d[g][2], d[g][3]);
        }
    }
    // ---- rowsum: thread pair (even,odd) covered one row ----
    rsum += __shfl_xor_sync(0xffffffffu, rsum, 1);
    if ((tid & 1) == 0)
        g_rowsum[s * M_ + row0 + xrow] = rsum;
#undef LOAD_X
#undef CONV_STORE
#undef CP_W
}

// ---------------------------------------------------------------------------
// Kernel 2: fused reduce + input projections.
//   Block = 64 embed rows. Phase 1: reduce 18 split partials + rowsum ->
//   embed tile in smem. Phase 2: all 3 projections.
// ---------------------------------------------------------------------------
__global__ void __launch_bounds__(256) k_reduce_proj(const float* __restrict__ Wir,
                                                     const float* __restrict__ Wiz,
                                                     const float* __restrict__ Win,
                                                     const float* __restrict__ bir,
                                                     const float* __restrict__ biz,
                                                     const float* __restrict__ bin)
{
    __shared__ float es[64 * 65];   // embed rows, padded
    __shared__ float inv_rs[64];
    __shared__ float wt[64 * 64];   // wt[e*64 + j] = W[j][e] (per-mat reuse)

    const int tid = threadIdx.x;
    const int r0  = blockIdx.x * 64;

    if (tid < 64) {
        float rs = 0.f;
        #pragma unroll
        for (int s = 0; s < KSPLIT; s++) rs += g_rowsum[s * M_ + r0 + tid];
        inv_rs[tid] = rs;
    }
    __syncthreads();

    #pragma unroll
    for (int i = 0; i < 4; i++) {
        int idx = tid + i * 256;          // 1024 float4 slots
        int row = idx >> 4;
        int c4  = idx & 15;
        float4 acc = make_float4(0.f, 0.f, 0.f, 0.f);
        #pragma unroll
        for (int s = 0; s < KSPLIT; s++) {
            float4 v = *(const float4*)(g_partial +
                        ((size_t)s * M_ + r0 + row) * 64 + 4 * c4);
            acc.x += v.x; acc.y += v.y; acc.z += v.z; acc.w += v.w;
        }
        float rs = inv_rs[row];
        es[row * 65 + 4 * c4 + 0] = fmaxf(acc.x / rs, 0.f);
        es[row * 65 + 4 * c4 + 1] = fmaxf(acc.y / rs, 0.f);
        es[row * 65 + 4 * c4 + 2] = fmaxf(acc.z / rs, 0.f);
        es[row * 65 + 4 * c4 + 3] = fmaxf(acc.w / rs, 0.f);
    }

    const int tx = tid & 15, ty = tid >> 4;

    #pragma unroll
    for (int mat = 0; mat < 3; mat++) {
        const float* W  = (mat == 0) ? Wir : (mat == 1) ? Wiz : Win;
        const float* bb = (mat == 0) ? bir : (mat == 1) ? biz : bin;

        __syncthreads();
        #pragma unroll
        for (int i = 0; i < 16; i++) {
            int flat = tid + i * 256;
            int r = flat >> 6, c = flat & 63;
            wt[c * 64 + r] = W[flat];
        }
        __syncthreads();

        float accf[4][4] = {};
        #pragma unroll
        for (int e = 0; e < 64; e++) {
            float a0 = es[(4 * ty + 0) * 65 + e];
            float a1 = es[(4 * ty + 1) * 65 + e];
            float a2 = es[(4 * ty + 2) * 65 + e];
            float a3 = es[(4 * ty + 3) * 65 + e];
            float w0 = wt[e * 64 + 4 * tx + 0];
            float w1 = wt[e * 64 + 4 * tx + 1];
            float w2 = wt[e * 64 + 4 * tx + 2];
            float w3 = wt[e * 64 + 4 * tx + 3];
            accf[0][0] = fmaf(a0, w0, accf[0][0]); accf[0][1] = fmaf(a0, w1, accf[0][1]);
            accf[0][2] = fmaf(a0, w2, accf[0][2]); accf[0][3] = fmaf(a0, w3, accf[0][3]);
            accf[1][0] = fmaf(a1, w0, accf[1][0]); accf[1][1] = fmaf(a1, w1, accf[1][1]);
            accf[1][2] = fmaf(a1, w2, accf[1][2]); accf[1][3] = fmaf(a1, w3, accf[1][3]);
            accf[2][0] = fmaf(a2, w0, accf[2][0]); accf[2][1] = fmaf(a2, w1, accf[2][1]);
            accf[2][2] = fmaf(a2, w2, accf[2][2]); accf[2][3] = fmaf(a2, w3, accf[2][3]);
            accf[3][0] = fmaf(a3, w0, accf[3][0]); accf[3][1] = fmaf(a3, w1, accf[3][1]);
            accf[3][2] = fmaf(a3, w2, accf[3][2]); accf[3][3] = fmaf(a3, w3, accf[3][3]);
        }
        float b0 = bb[4 * tx + 0], b1 = bb[4 * tx + 1];
        float b2 = bb[4 * tx + 2], b3 = bb[4 * tx + 3];
        #pragma unroll
        for (int i = 0; i < 4; i++) {
            int row = r0 + 4 * ty + i;
            float* o = g_proj + (size_t)mat * (M_ * 64) + row * 64 + 4 * tx;
            o[0] = accf[i][0] + b0;
            o[1] = accf[i][1] + b1;
            o[2] = accf[i][2] + b2;
            o[3] = accf[i][3] + b3;
        }
    }
}

// ---------------------------------------------------------------------------
// Kernel 3: per-batch GRU scan + head (proj staged in smem, weights in regs)
// ---------------------------------------------------------------------------
#define GRU_SMEM ((3 * 4096 + 128) * 4)

__device__ __forceinline__ float sigm(float v) {
    return __fdividef(1.f, 1.f + __expf(-v));
}
__device__ __forceinline__ float tanh_fast(float v) {
    float e = __expf(2.f * v);
    return __fdividef(e - 1.f, e + 1.f);
}

__global__ void __launch_bounds__(256) k_gru(const float* __restrict__ Whr,
                                             const float* __restrict__ Whz,
                                             const float* __restrict__ Whn,
                                             const float* __restrict__ bhr_g,
                                             const float* __restrict__ bhz_g,
                                             const float* __restrict__ bhn_g,
                                             const float* __restrict__ Wout,
                                             const float* __restrict__ bout,
                                             float* __restrict__ out)
{
    extern __shared__ float sp[];
    float* sr = sp;
    float* sz = sp + 4096;
    float* sn = sp + 8192;
    float* ha = sp + 12288;
    float* hb = ha + 64;

    const int tid = threadIdx.x;
    const int j   = tid >> 2;
    const int q   = tid & 3;
    const int b   = blockIdx.x;

    #pragma unroll
    for (int m = 0; m < 3; m++) {
        const float4* src = (const float4*)(g_proj + (size_t)m * (M_ * 64) + b * 4096);
        float4* dst = (float4*)(sp + m * 4096);
        #pragma unroll
        for (int i = 0; i < 4; i++) {
            int idx = tid + i * 256;
            dst[idx] = src[idx];
        }
    }

    float4 wr[4], wz[4], wn[4];
    {
        const float4* r4 = (const float4*)(Whr + j * 64 + q * 16);
        const float4* z4 = (const float4*)(Whz + j * 64 + q * 16);
        const float4* n4 = (const float4*)(Whn + j * 64 + q * 16);
        #pragma unroll
        for (int u = 0; u < 4; u++) { wr[u] = r4[u]; wz[u] = z4[u]; wn[u] = n4[u]; }
    }
    const float bhr = bhr_g[j], bhz = bhz_g[j], bhn = bhn_g[j];
    __syncthreads();

    {
        float z1 = sigm(sz[j]);
        float n1 = tanh_fast(sn[j]);
        if (q == 0) ha[j] = (1.f - z1) * n1;
    }
    __syncthreads();

    float* hc = ha;
    float* hx = hb;
    for (int t = 1; t < T_; t++) {
        float xr = sr[t * 64 + j];
        float xz = sz[t * 64 + j];
        float xn = sn[t * 64 + j];

        const float4* h4 = (const float4*)(hc + q * 16);
        float4 hv0 = h4[0], hv1 = h4[1], hv2 = h4[2], hv3 = h4[3];

        float ar0 = 0.f, az0 = 0.f, an0 = 0.f;
        float ar1 = 0.f, az1 = 0.f, an1 = 0.f;
        ar0 = fmaf(wr[0].x, hv0.x, ar0); az0 = fmaf(wz[0].x, hv0.x, az0); an0 = fmaf(wn[0].x, hv0.x, an0);
        ar0 = fmaf(wr[0].y, hv0.y, ar0); az0 = fmaf(wz[0].y, hv0.y, az0); an0 = fmaf(wn[0].y, hv0.y, an0);
        ar0 = fmaf(wr[0].z, hv0.z, ar0); az0 = fmaf(wz[0].z, hv0.z, az0); an0 = fmaf(wn[0].z, hv0.z, an0);
        ar0 = fmaf(wr[0].w, hv0.w, ar0); az0 = fmaf(wz[0].w, hv0.w, az0); an0 = fmaf(wn[0].w, hv0.w, an0);
        ar1 = fmaf(wr[1].x, hv1.x, ar1); az1 = fmaf(wz[1].x, hv1.x, az1); an1 = fmaf(wn[1].x, hv1.x, an1);
        ar1 = fmaf(wr[1].y, hv1.y, ar1); az1 = fmaf(wz[1].y, hv1.y, az1); an1 = fmaf(wn[1].y, hv1.y, an1);
        ar1 = fmaf(wr[1].z, hv1.z, ar1); az1 = fmaf(wz[1].z, hv1.z, az1); an1 = fmaf(wn[1].z, hv1.z, an1);
        ar1 = fmaf(wr[1].w, hv1.w, ar1); az1 = fmaf(wz[1].w, hv1.w, az1); an1 = fmaf(wn[1].w, hv1.w, an1);
        ar0 = fmaf(wr[2].x, hv2.x, ar0); az0 = fmaf(wz[2].x, hv2.x, az0); an0 = fmaf(wn[2].x, hv2.x, an0);
        ar0 = fmaf(wr[2].y, hv2.y, ar0); az0 = fmaf(wz[2].y, hv2.y, az0); an0 = fmaf(wn[2].y, hv2.y, an0);
        ar0 = fmaf(wr[2].z, hv2.z, ar0); az0 = fmaf(wz[2].z, hv2.z, az0); an0 = fmaf(wn[2].z, hv2.z, an0);
        ar0 = fmaf(wr[2].w, hv2.w, ar0); az0 = fmaf(wz[2].w, hv2.w, az0); an0 = fmaf(wn[2].w, hv2.w, an0);
        ar1 = fmaf(wr[3].x, hv3.x, ar1); az1 = fmaf(wz[3].x, hv3.x, az1); an1 = fmaf(wn[3].x, hv3.x, an1);
        ar1 = fmaf(wr[3].y, hv3.y, ar1); az1 = fmaf(wz[3].y, hv3.y, az1); an1 = fmaf(wn[3].y, hv3.y, an1);
        ar1 = fmaf(wr[3].z, hv3.z, ar1); az1 = fmaf(wz[3].z, hv3.z, az1); an1 = fmaf(wn[3].z, hv3.z, an1);
        ar1 = fmaf(wr[3].w, hv3.w, ar1); az1 = fmaf(wz[3].w, hv3.w, az1); an1 = fmaf(wn[3].w, hv3.w, an1);
        float ar = ar0 + ar1, az = az0 + az1, an = an0 + an1;

        ar += __shfl_xor_sync(0xffffffffu, ar, 1);
        az += __shfl_xor_sync(0xffffffffu, az, 1);
        an += __shfl_xor_sync(0xffffffffu, an, 1);
        ar += __shfl_xor_sync(0xffffffffu, ar, 2);
        az += __shfl_xor_sync(0xffffffffu, az, 2);
        an += __shfl_xor_sync(0xffffffffu, an, 2);
        ar += bhr; az += bhz; an += bhn;

        float r = sigm(xr + ar);
        float z = sigm(xz + az);
        float n = tanh_fast(xn + r * ar);
        float hold = hc[j];
        float hnew = (1.f - z) * n + z * hold;
        if (q == 0) hx[j] = hnew;
        __syncthreads();
        float* tmp = hc; hc = hx; hx = tmp;
    }

    if (tid < O_) {
        float acc = bout[tid];
        #pragma unroll
        for (int k = 0; k < 64; k++) acc = fmaf(hc[k], Wout[tid * 64 + k], acc);
        out[b * O_ + tid] = acc;
    }
}

// ---------------------------------------------------------------------------
// Launch
// ---------------------------------------------------------------------------
extern "C" void kernel_launch(void* const* d_in, const int* in_sizes, int n_in,
                              void* d_out, int out_size)
{
    const float* x    = (const float*)d_in[0];
    const float* ve   = (const float*)d_in[1];
    const float* Wir  = (const float*)d_in[2];
    const float* Wiz  = (const float*)d_in[3];
    const float* Win  = (const float*)d_in[4];
    const float* Whr  = (const float*)d_in[5];
    const float* Whz  = (const float*)d_in[6];
    const float* Whn  = (const float*)d_in[7];
    const float* bir  = (const float*)d_in[8];
    const float* biz  = (const float*)d_in[9];
    const float* bin  = (const float*)d_in[10];
    const float* bhr  = (const float*)d_in[11];
    const float* bhz  = (const float*)d_in[12];
    const float* bhn  = (const float*)d_in[13];
    const float* Wout = (const float*)d_in[14];
    const float* bout = (const float*)d_in[15];
    (void)in_sizes; (void)n_in; (void)out_size;

    cudaFuncSetAttribute(k_gru, cudaFuncAttributeMaxDynamicSharedMemorySize,
                         GRU_SMEM);

    k_wsplit<<<NTILES, 256>>>(ve);
    k_embed_gemm<<<dim3(16, KSPLIT), 256>>>(x);
    k_reduce_proj<<<32, 256>>>(Wir, Wiz, Win, bir, biz, bin);
    k_gru<<<32, 256, GRU_SMEM>>>(Whr, Whz, Whn, bhr, bhz, bhn, Wout, bout,
                                 (float*)d_out);
}